// round 13
// baseline (speedup 1.0000x reference)
#include <cuda_runtime.h>
#include <cuda_fp16.h>
#include <mma.h>
#include <cstdint>

#define N_NODES 100000
#define N_PAD   100096        // multiple of 128-row tiles
#define N_EDGES 1600000
#define D 128
#define SCAN_B 1024
#define N_SCAN_BLOCKS ((N_NODES + SCAN_B - 1) / SCAN_B)   // 98

using namespace nvcuda;

// Scratch (allocation-free rule: __device__ globals; zero-initialized)
__device__ __half g_hs[(size_t)N_PAD * D];   // hs = (x @ W) * dinv[row], fp16
__device__ __half g_xh[(size_t)N_PAD * D];   // activations, fp16 (pad rows 0)
__device__ __half g_w16[3 * D * D];          // weights, fp16
__device__ float  g_dinv[N_NODES];
__device__ int    g_is64;
__device__ unsigned g_epack[N_EDGES];        // (col<<15) | slot
__device__ int    g_cnt[N_NODES];
__device__ int    g_rowptr[N_NODES + 1];
__device__ int    g_src[N_EDGES];
__device__ int    g_bsum[N_SCAN_BLOCKS];

// ===========================================================================
// Setup
// ===========================================================================

// zero cnt + convert W to fp16; block 0 additionally detects edge dtype
__global__ void k_detect_zero_w(const unsigned int* __restrict__ buf,
                                const float* __restrict__ Ws) {
    int i = blockIdx.x * blockDim.x + threadIdx.x;
    if (i < N_NODES) g_cnt[i] = 0;
    if (i < 3 * D * D) g_w16[i] = __float2half_rn(Ws[i]);
    if (blockIdx.x == 0) {
        __shared__ unsigned int acc;
        if (threadIdx.x == 0) acc = 0u;
        __syncthreads();
        unsigned int local = 0u;
        for (int k = threadIdx.x; k < 4096; k += blockDim.x)
            local |= buf[2 * k + 1];
        atomicOr(&acc, local);
        __syncthreads();
        if (threadIdx.x == 0) g_is64 = (acc == 0u) ? 1 : 0;
    }
}

// histogram target degree; the atomic return value doubles as the CSR slot
__global__ void k_hist_pack(const void* __restrict__ buf) {
    int e = blockIdx.x * blockDim.x + threadIdx.x;
    if (e >= N_EDGES) return;
    int c;
    if (g_is64) c = (int)((const long long*)buf)[e + N_EDGES];
    else        c = ((const int*)buf)[e + N_EDGES];
    int pos = atomicAdd(&g_cnt[c], 1);
    g_epack[e] = ((unsigned)c << 15) | ((unsigned)pos & 0x7FFFu);
}

// block-level exclusive scan of degrees; also dinv = rsqrt(1+deg)
__global__ void __launch_bounds__(SCAN_B)
k_scan1() {
    __shared__ int s[SCAN_B];
    int i = blockIdx.x * SCAN_B + threadIdx.x;
    int v = (i < N_NODES) ? g_cnt[i] : 0;
    if (i < N_NODES) g_dinv[i] = rsqrtf(1.0f + (float)v);
    s[threadIdx.x] = v;
    __syncthreads();
#pragma unroll
    for (int off = 1; off < SCAN_B; off <<= 1) {
        int t = (threadIdx.x >= off) ? s[threadIdx.x - off] : 0;
        __syncthreads();
        s[threadIdx.x] += t;
        __syncthreads();
    }
    if (i < N_NODES) g_rowptr[i] = s[threadIdx.x] - v;
    if (threadIdx.x == SCAN_B - 1) g_bsum[blockIdx.x] = s[SCAN_B - 1];
}

// every block redundantly scans the 98 block sums, then applies to its nodes
__global__ void k_scan23() {
    __shared__ int s[128];
    __shared__ int ex[128];
    int t = threadIdx.x;
    int v = 0;
    if (t < 128) {
        v = (t < N_SCAN_BLOCKS) ? g_bsum[t] : 0;
        s[t] = v;
    }
    __syncthreads();
#pragma unroll
    for (int off = 1; off < 128; off <<= 1) {
        int tv = 0;
        if (t < 128 && t >= off) tv = s[t - off];
        __syncthreads();
        if (t < 128) s[t] += tv;
        __syncthreads();
    }
    if (t < 128) ex[t] = s[t] - v;   // exclusive
    __syncthreads();
    int i = blockIdx.x * blockDim.x + t;
    if (i < N_NODES) g_rowptr[i] += ex[i >> 10];
    if (i == 0) g_rowptr[N_NODES] = N_EDGES;
}

// atomic-free CSR fill using the packed (col, slot)
__global__ void k_fill(const void* __restrict__ buf) {
    int e = blockIdx.x * blockDim.x + threadIdx.x;
    if (e >= N_EDGES) return;
    unsigned p = g_epack[e];
    int c = (int)(p >> 15);
    int pos = (int)(p & 0x7FFFu);
    int r;
    if (g_is64) r = (int)((const long long*)buf)[e];
    else        r = ((const int*)buf)[e];
    int idx = g_rowptr[c] + pos;
    if (idx < N_EDGES) g_src[idx] = r;
}

// ===========================================================================
// fp16 wmma GEMM (unchanged from R12): 128x128 tile, conflict-free LDSM.
// ===========================================================================
#define LDH 136
#define GEMM_SMEM (2 * 128 * LDH * 2)      // 69632 B

template<bool FROM_EMB>
__global__ void __launch_bounds__(256, 2)
k_gemm(const __half* __restrict__ Wl, const float* __restrict__ emb) {
    extern __shared__ __half smh[];
    __half* As = smh;                 // [128][LDH]
    __half* Wsm = smh + 128 * LDH;    // [128][LDH]

    const int tid = threadIdx.x;
    const int wid = tid >> 5;
    const int lane = tid & 31;
    const int wm = wid >> 1;
    const int wn = wid & 1;
    const int row0 = blockIdx.x * 128;

    for (int idx = tid; idx < 2048; idx += 256) {
        int r = idx >> 4, c8 = idx & 15;
        uint4 v = ((const uint4*)(Wl + r * D))[c8];
        *(uint4*)(Wsm + r * LDH + c8 * 8) = v;
    }
    for (int idx = tid; idx < 2048; idx += 256) {
        int r = idx >> 4, c8 = idx & 15;
        int row = row0 + r;
        uint4 v = make_uint4(0u, 0u, 0u, 0u);
        if (row < N_NODES) {
            if (FROM_EMB) {
                const float4* s = (const float4*)(emb + (size_t)row * D) + c8 * 2;
                float4 v0 = s[0], v1 = s[1];
                __half2 h;
                h = __floats2half2_rn(v0.x, v0.y); v.x = *(uint32_t*)&h;
                h = __floats2half2_rn(v0.z, v0.w); v.y = *(uint32_t*)&h;
                h = __floats2half2_rn(v1.x, v1.y); v.z = *(uint32_t*)&h;
                h = __floats2half2_rn(v1.z, v1.w); v.w = *(uint32_t*)&h;
            } else {
                v = ((const uint4*)(g_xh + (size_t)row * D))[c8];
            }
        }
        *(uint4*)(As + r * LDH + c8 * 8) = v;
    }
    __syncthreads();

    wmma::fragment<wmma::accumulator, 16, 16, 16, float> acc[2][4];
#pragma unroll
    for (int i = 0; i < 2; i++)
#pragma unroll
        for (int j = 0; j < 4; j++) wmma::fill_fragment(acc[i][j], 0.0f);

#pragma unroll
    for (int k = 0; k < 8; k++) {
        wmma::fragment<wmma::matrix_a, 16, 16, 16, __half, wmma::row_major> a[2];
        wmma::fragment<wmma::matrix_b, 16, 16, 16, __half, wmma::row_major> b[4];
#pragma unroll
        for (int i = 0; i < 2; i++)
            wmma::load_matrix_sync(a[i], As + (wm * 32 + i * 16) * LDH + k * 16,
                                   LDH);
#pragma unroll
        for (int j = 0; j < 4; j++)
            wmma::load_matrix_sync(b[j], Wsm + (k * 16) * LDH + wn * 64 + j * 16,
                                   LDH);
#pragma unroll
        for (int i = 0; i < 2; i++)
#pragma unroll
            for (int j = 0; j < 4; j++)
                wmma::mma_sync(acc[i][j], a[i], b[j], acc[i][j]);
    }

    __syncthreads();
    float* stage = reinterpret_cast<float*>(smh) + wid * (16 * 68);
#pragma unroll
    for (int i = 0; i < 2; i++) {
#pragma unroll
        for (int j = 0; j < 4; j++)
            wmma::store_matrix_sync(stage + j * 16, acc[i][j], 68,
                                    wmma::mem_row_major);
        __syncwarp();
        int r = lane >> 1;
        int ch = (lane & 1) * 32;
        int row = row0 + wm * 32 + i * 16 + r;
        float s = (row < N_NODES) ? g_dinv[row] : 0.0f;
        const float* src = stage + r * 68 + ch;
        if (row < N_NODES) {
            uint4* dst = (uint4*)(g_hs + (size_t)row * D + wn * 64 + ch);
#pragma unroll
            for (int q = 0; q < 4; q++) {
                uint4 o;
                __half2 h;
                h = __floats2half2_rn(src[q * 8 + 0] * s, src[q * 8 + 1] * s);
                o.x = *(uint32_t*)&h;
                h = __floats2half2_rn(src[q * 8 + 2] * s, src[q * 8 + 3] * s);
                o.y = *(uint32_t*)&h;
                h = __floats2half2_rn(src[q * 8 + 4] * s, src[q * 8 + 5] * s);
                o.z = *(uint32_t*)&h;
                h = __floats2half2_rn(src[q * 8 + 6] * s, src[q * 8 + 7] * s);
                o.w = *(uint32_t*)&h;
                dst[q] = o;
            }
        }
        __syncwarp();
    }
}

// ===========================================================================
// Aggregation v2: warp per node; TWO half-warps gather DIFFERENT edges
// concurrently, each lane loads uint4 (8 cols). 2-deep unroll per half
// -> 4 row-gathers in flight per warp. fp32 accumulate, shfl_down combine.
// ===========================================================================
__device__ __forceinline__ void add_row(float2 (&a)[4], uint4 v) {
    float2 t;
    t = __half22float2(*(__half2*)&v.x); a[0].x += t.x; a[0].y += t.y;
    __half2 h1 = *(__half2*)(((uint32_t*)&v.x) + 1);
    // note: uint4 fields x,y,z,w are 4 half2s
    t = __half22float2(*(__half2*)&v.y); a[1].x += t.x; a[1].y += t.y;
    t = __half22float2(*(__half2*)&v.z); a[2].x += t.x; a[2].y += t.y;
    t = __half22float2(*(__half2*)&v.w); a[3].x += t.x; a[3].y += t.y;
    (void)h1;
}

__global__ void __launch_bounds__(256)
k_aggregate(const float* __restrict__ bias, float* __restrict__ out,
            int use_out) {
    int node = (blockIdx.x * blockDim.x + threadIdx.x) >> 5;
    int lane = threadIdx.x & 31;
    if (node >= N_NODES) return;
    const int half = lane >> 4;       // 0 or 1
    const int hl = lane & 15;         // uint4 index within row (8 cols)

    float dinv_c = g_dinv[node];
    const uint4* HS4 = (const uint4*)g_hs;   // 16 uint4 per row

    float2 accA[4] = {{0,0},{0,0},{0,0},{0,0}};
    float2 accB[4] = {{0,0},{0,0},{0,0},{0,0}};

    // self term: counted once (half 0 only)
    if (half == 0)
        add_row(accA, HS4[(size_t)node * 16 + hl]);

    int beg = g_rowptr[node];
    int end = g_rowptr[node + 1];
    for (int base = beg; base < end; base += 32) {
        int j = base + lane;
        int r = (j < end) ? g_src[j] : 0;
        int cnt = min(32, end - base);
        for (int k = 0; k < cnt; k += 4) {
            int i0 = k + half;        // edges k,k+1 -> halves 0,1
            int i1 = k + 2 + half;    // edges k+2,k+3
            int r0 = __shfl_sync(0xffffffffu, r, i0 & 31);
            int r1 = __shfl_sync(0xffffffffu, r, i1 & 31);
            if (i0 < cnt) add_row(accA, HS4[(size_t)r0 * 16 + hl]);
            if (i1 < cnt) add_row(accB, HS4[(size_t)r1 * 16 + hl]);
        }
    }

    // combine the two half-warps (lane hl += lane hl+16)
#pragma unroll
    for (int q = 0; q < 4; q++) {
        accA[q].x += accB[q].x;
        accA[q].y += accB[q].y;
        accA[q].x += __shfl_down_sync(0xffffffffu, accA[q].x, 16);
        accA[q].y += __shfl_down_sync(0xffffffffu, accA[q].y, 16);
    }

    if (half == 0) {
        float4 b0 = ((const float4*)bias)[hl * 2];
        float4 b1 = ((const float4*)bias)[hl * 2 + 1];
        float o[8];
        o[0] = fmaxf(fmaf(dinv_c, accA[0].x, b0.x), 0.f);
        o[1] = fmaxf(fmaf(dinv_c, accA[0].y, b0.y), 0.f);
        o[2] = fmaxf(fmaf(dinv_c, accA[1].x, b0.z), 0.f);
        o[3] = fmaxf(fmaf(dinv_c, accA[1].y, b0.w), 0.f);
        o[4] = fmaxf(fmaf(dinv_c, accA[2].x, b1.x), 0.f);
        o[5] = fmaxf(fmaf(dinv_c, accA[2].y, b1.y), 0.f);
        o[6] = fmaxf(fmaf(dinv_c, accA[3].x, b1.z), 0.f);
        o[7] = fmaxf(fmaf(dinv_c, accA[3].y, b1.w), 0.f);
        if (use_out) {
            float4* dst = (float4*)(out + (size_t)node * D + hl * 8);
            dst[0] = make_float4(o[0], o[1], o[2], o[3]);
            dst[1] = make_float4(o[4], o[5], o[6], o[7]);
        } else {
            uint4 v;
            __half2 h;
            h = __floats2half2_rn(o[0], o[1]); v.x = *(uint32_t*)&h;
            h = __floats2half2_rn(o[2], o[3]); v.y = *(uint32_t*)&h;
            h = __floats2half2_rn(o[4], o[5]); v.z = *(uint32_t*)&h;
            h = __floats2half2_rn(o[6], o[7]); v.w = *(uint32_t*)&h;
            ((uint4*)(g_xh + (size_t)node * D))[hl] = v;
        }
    }
}

// ===========================================================================
// Launch
// ===========================================================================
extern "C" void kernel_launch(void* const* d_in, const int* in_sizes, int n_in,
                              void* d_out, int out_size) {
    const void* edge = d_in[0];
    const float* emb = (const float*)d_in[1];
    const float* Ws  = (const float*)d_in[2];
    const float* bs  = (const float*)d_in[3];
    float* out = (float*)d_out;

    __half* g_w16_p;
    cudaGetSymbolAddress((void**)&g_w16_p, g_w16);

    static bool attr_done = false;
    if (!attr_done) {
        cudaFuncSetAttribute(k_gemm<true>,
                             cudaFuncAttributeMaxDynamicSharedMemorySize, GEMM_SMEM);
        cudaFuncSetAttribute(k_gemm<false>,
                             cudaFuncAttributeMaxDynamicSharedMemorySize, GEMM_SMEM);
        attr_done = true;
    }

    const int nb_nodes = (N_NODES + 255) / 256;
    const int nb_edges = (N_EDGES + 255) / 256;

    k_detect_zero_w<<<nb_nodes, 256>>>((const unsigned int*)edge, Ws);
    k_hist_pack<<<nb_edges, 256>>>(edge);
    k_scan1<<<N_SCAN_BLOCKS, SCAN_B>>>();
    k_scan23<<<nb_nodes, 256>>>();
    k_fill<<<nb_edges, 256>>>(edge);

    const int gemm_blocks = N_PAD / 128;                 // 782
    const int agg_blocks = (N_NODES * 32 + 255) / 256;   // 12500

    // Layer 0 (reads emb fp32 directly)
    k_gemm<true><<<gemm_blocks, 256, GEMM_SMEM>>>(g_w16_p + 0 * D * D, emb);
    k_aggregate<<<agg_blocks, 256>>>(bs + 0 * D, out, 0);
    // Layer 1
    k_gemm<false><<<gemm_blocks, 256, GEMM_SMEM>>>(g_w16_p + 1 * D * D, nullptr);
    k_aggregate<<<agg_blocks, 256>>>(bs + 1 * D, out, 0);
    // Layer 2 -> d_out (ReLU in aggregate)
    k_gemm<false><<<gemm_blocks, 256, GEMM_SMEM>>>(g_w16_p + 2 * D * D, nullptr);
    k_aggregate<<<agg_blocks, 256>>>(bs + 2 * D, out, 1);
}

// round 14
// speedup vs baseline: 1.0451x; 1.0451x over previous
#include <cuda_runtime.h>
#include <cuda_fp16.h>
#include <mma.h>
#include <cstdint>

#define N_NODES 100000
#define N_PAD   100096        // multiple of 128-row tiles
#define N_EDGES 1600000
#define D 128
#define SCAN_B 1024
#define N_SCAN_BLOCKS ((N_NODES + SCAN_B - 1) / SCAN_B)   // 98

using namespace nvcuda;

// Scratch (allocation-free rule: __device__ globals; zero-initialized)
__device__ __half g_hs[(size_t)N_PAD * D];   // hs = (x @ W) * dinv[row], fp16
__device__ __half g_xh[(size_t)N_PAD * D];   // activations, fp16 (pad rows 0)
__device__ __half g_w16[3 * D * D];          // weights, fp16
__device__ float  g_dinv[N_NODES];
__device__ int    g_is64;
__device__ unsigned g_epack[N_EDGES];        // (col<<15) | slot
__device__ int    g_cnt[N_NODES];
__device__ int    g_rowptr[N_NODES + 1];
__device__ int    g_src[N_EDGES];
__device__ int    g_bsum[N_SCAN_BLOCKS];

// ===========================================================================
// Setup
// ===========================================================================

// zero cnt + convert W to fp16; block 0 additionally detects edge dtype
__global__ void k_detect_zero_w(const unsigned int* __restrict__ buf,
                                const float* __restrict__ Ws) {
    int i = blockIdx.x * blockDim.x + threadIdx.x;
    if (i < N_NODES) g_cnt[i] = 0;
    if (i < 3 * D * D) g_w16[i] = __float2half_rn(Ws[i]);
    if (blockIdx.x == 0) {
        __shared__ unsigned int acc;
        if (threadIdx.x == 0) acc = 0u;
        __syncthreads();
        unsigned int local = 0u;
        for (int k = threadIdx.x; k < 4096; k += blockDim.x)
            local |= buf[2 * k + 1];
        atomicOr(&acc, local);
        __syncthreads();
        if (threadIdx.x == 0) g_is64 = (acc == 0u) ? 1 : 0;
    }
}

// histogram target degree; the atomic return value doubles as the CSR slot
__global__ void k_hist_pack(const void* __restrict__ buf) {
    int e = blockIdx.x * blockDim.x + threadIdx.x;
    if (e >= N_EDGES) return;
    int c;
    if (g_is64) c = (int)((const long long*)buf)[e + N_EDGES];
    else        c = ((const int*)buf)[e + N_EDGES];
    int pos = atomicAdd(&g_cnt[c], 1);
    g_epack[e] = ((unsigned)c << 15) | ((unsigned)pos & 0x7FFFu);
}

// block-level exclusive scan of degrees; also dinv = rsqrt(1+deg)
__global__ void __launch_bounds__(SCAN_B)
k_scan1() {
    __shared__ int s[SCAN_B];
    int i = blockIdx.x * SCAN_B + threadIdx.x;
    int v = (i < N_NODES) ? g_cnt[i] : 0;
    if (i < N_NODES) g_dinv[i] = rsqrtf(1.0f + (float)v);
    s[threadIdx.x] = v;
    __syncthreads();
#pragma unroll
    for (int off = 1; off < SCAN_B; off <<= 1) {
        int t = (threadIdx.x >= off) ? s[threadIdx.x - off] : 0;
        __syncthreads();
        s[threadIdx.x] += t;
        __syncthreads();
    }
    if (i < N_NODES) g_rowptr[i] = s[threadIdx.x] - v;
    if (threadIdx.x == SCAN_B - 1) g_bsum[blockIdx.x] = s[SCAN_B - 1];
}

// every block redundantly scans the 98 block sums, then applies to its nodes
__global__ void k_scan23() {
    __shared__ int s[128];
    __shared__ int ex[128];
    int t = threadIdx.x;
    int v = 0;
    if (t < 128) {
        v = (t < N_SCAN_BLOCKS) ? g_bsum[t] : 0;
        s[t] = v;
    }
    __syncthreads();
#pragma unroll
    for (int off = 1; off < 128; off <<= 1) {
        int tv = 0;
        if (t < 128 && t >= off) tv = s[t - off];
        __syncthreads();
        if (t < 128) s[t] += tv;
        __syncthreads();
    }
    if (t < 128) ex[t] = s[t] - v;   // exclusive
    __syncthreads();
    int i = blockIdx.x * blockDim.x + t;
    if (i < N_NODES) g_rowptr[i] += ex[i >> 10];
    if (i == 0) g_rowptr[N_NODES] = N_EDGES;
}

// atomic-free CSR fill using the packed (col, slot)
__global__ void k_fill(const void* __restrict__ buf) {
    int e = blockIdx.x * blockDim.x + threadIdx.x;
    if (e >= N_EDGES) return;
    unsigned p = g_epack[e];
    int c = (int)(p >> 15);
    int pos = (int)(p & 0x7FFFu);
    int r;
    if (g_is64) r = (int)((const long long*)buf)[e];
    else        r = ((const int*)buf)[e];
    int idx = g_rowptr[c] + pos;
    if (idx < N_EDGES) g_src[idx] = r;
}

// ===========================================================================
// fp16 wmma GEMM (unchanged, proven): 128x128 tile, conflict-free LDSM.
// ===========================================================================
#define LDH 136
#define GEMM_SMEM (2 * 128 * LDH * 2)      // 69632 B

template<bool FROM_EMB>
__global__ void __launch_bounds__(256, 2)
k_gemm(const __half* __restrict__ Wl, const float* __restrict__ emb) {
    extern __shared__ __half smh[];
    __half* As = smh;                 // [128][LDH]
    __half* Wsm = smh + 128 * LDH;    // [128][LDH]

    const int tid = threadIdx.x;
    const int wid = tid >> 5;
    const int lane = tid & 31;
    const int wm = wid >> 1;
    const int wn = wid & 1;
    const int row0 = blockIdx.x * 128;

    for (int idx = tid; idx < 2048; idx += 256) {
        int r = idx >> 4, c8 = idx & 15;
        uint4 v = ((const uint4*)(Wl + r * D))[c8];
        *(uint4*)(Wsm + r * LDH + c8 * 8) = v;
    }
    for (int idx = tid; idx < 2048; idx += 256) {
        int r = idx >> 4, c8 = idx & 15;
        int row = row0 + r;
        uint4 v = make_uint4(0u, 0u, 0u, 0u);
        if (row < N_NODES) {
            if (FROM_EMB) {
                const float4* s = (const float4*)(emb + (size_t)row * D) + c8 * 2;
                float4 v0 = s[0], v1 = s[1];
                __half2 h;
                h = __floats2half2_rn(v0.x, v0.y); v.x = *(uint32_t*)&h;
                h = __floats2half2_rn(v0.z, v0.w); v.y = *(uint32_t*)&h;
                h = __floats2half2_rn(v1.x, v1.y); v.z = *(uint32_t*)&h;
                h = __floats2half2_rn(v1.z, v1.w); v.w = *(uint32_t*)&h;
            } else {
                v = ((const uint4*)(g_xh + (size_t)row * D))[c8];
            }
        }
        *(uint4*)(As + r * LDH + c8 * 8) = v;
    }
    __syncthreads();

    wmma::fragment<wmma::accumulator, 16, 16, 16, float> acc[2][4];
#pragma unroll
    for (int i = 0; i < 2; i++)
#pragma unroll
        for (int j = 0; j < 4; j++) wmma::fill_fragment(acc[i][j], 0.0f);

#pragma unroll
    for (int k = 0; k < 8; k++) {
        wmma::fragment<wmma::matrix_a, 16, 16, 16, __half, wmma::row_major> a[2];
        wmma::fragment<wmma::matrix_b, 16, 16, 16, __half, wmma::row_major> b[4];
#pragma unroll
        for (int i = 0; i < 2; i++)
            wmma::load_matrix_sync(a[i], As + (wm * 32 + i * 16) * LDH + k * 16,
                                   LDH);
#pragma unroll
        for (int j = 0; j < 4; j++)
            wmma::load_matrix_sync(b[j], Wsm + (k * 16) * LDH + wn * 64 + j * 16,
                                   LDH);
#pragma unroll
        for (int i = 0; i < 2; i++)
#pragma unroll
            for (int j = 0; j < 4; j++)
                wmma::mma_sync(acc[i][j], a[i], b[j], acc[i][j]);
    }

    __syncthreads();
    float* stage = reinterpret_cast<float*>(smh) + wid * (16 * 68);
#pragma unroll
    for (int i = 0; i < 2; i++) {
#pragma unroll
        for (int j = 0; j < 4; j++)
            wmma::store_matrix_sync(stage + j * 16, acc[i][j], 68,
                                    wmma::mem_row_major);
        __syncwarp();
        int r = lane >> 1;
        int ch = (lane & 1) * 32;
        int row = row0 + wm * 32 + i * 16 + r;
        float s = (row < N_NODES) ? g_dinv[row] : 0.0f;
        const float* src = stage + r * 68 + ch;
        if (row < N_NODES) {
            uint4* dst = (uint4*)(g_hs + (size_t)row * D + wn * 64 + ch);
#pragma unroll
            for (int q = 0; q < 4; q++) {
                uint4 o;
                __half2 h;
                h = __floats2half2_rn(src[q * 8 + 0] * s, src[q * 8 + 1] * s);
                o.x = *(uint32_t*)&h;
                h = __floats2half2_rn(src[q * 8 + 2] * s, src[q * 8 + 3] * s);
                o.y = *(uint32_t*)&h;
                h = __floats2half2_rn(src[q * 8 + 4] * s, src[q * 8 + 5] * s);
                o.z = *(uint32_t*)&h;
                h = __floats2half2_rn(src[q * 8 + 6] * s, src[q * 8 + 7] * s);
                o.w = *(uint32_t*)&h;
                dst[q] = o;
            }
        }
        __syncwarp();
    }
}

// ===========================================================================
// Aggregation (R12 proven shape, 4-deep unroll): one warp per node, full-warp
// uint2 gather per edge row, 4 independent accumulator sets -> 4 loads in
// flight. fp32 accumulate throughout.
// ===========================================================================
__global__ void __launch_bounds__(256)
k_aggregate(const float* __restrict__ bias, float* __restrict__ out,
            int use_out) {
    int node = (blockIdx.x * blockDim.x + threadIdx.x) >> 5;
    int lane = threadIdx.x & 31;
    if (node >= N_NODES) return;

    float dinv_c = g_dinv[node];
    const uint2* HS = (const uint2*)g_hs;   // 32 uint2 per row

    // self term
    uint2 v = HS[(size_t)node * 32 + lane];
    float2 f0 = __half22float2(*(__half2*)&v.x);
    float2 f1 = __half22float2(*(__half2*)&v.y);
    float4 a0 = make_float4(f0.x, f0.y, f1.x, f1.y);
    float4 a1 = make_float4(0.f, 0.f, 0.f, 0.f);
    float4 a2 = make_float4(0.f, 0.f, 0.f, 0.f);
    float4 a3 = make_float4(0.f, 0.f, 0.f, 0.f);

    int beg = g_rowptr[node];
    int end = g_rowptr[node + 1];
    for (int base = beg; base < end; base += 32) {
        int j = base + lane;
        int r = (j < end) ? g_src[j] : 0;
        int cnt = min(32, end - base);
        int k = 0;
        for (; k + 3 < cnt; k += 4) {
            int r0 = __shfl_sync(0xffffffffu, r, k);
            int r1 = __shfl_sync(0xffffffffu, r, k + 1);
            int r2 = __shfl_sync(0xffffffffu, r, k + 2);
            int r3 = __shfl_sync(0xffffffffu, r, k + 3);
            uint2 v0 = HS[(size_t)r0 * 32 + lane];
            uint2 v1 = HS[(size_t)r1 * 32 + lane];
            uint2 v2 = HS[(size_t)r2 * 32 + lane];
            uint2 v3 = HS[(size_t)r3 * 32 + lane];
            float2 p, q;
            p = __half22float2(*(__half2*)&v0.x);
            q = __half22float2(*(__half2*)&v0.y);
            a0.x += p.x; a0.y += p.y; a0.z += q.x; a0.w += q.y;
            p = __half22float2(*(__half2*)&v1.x);
            q = __half22float2(*(__half2*)&v1.y);
            a1.x += p.x; a1.y += p.y; a1.z += q.x; a1.w += q.y;
            p = __half22float2(*(__half2*)&v2.x);
            q = __half22float2(*(__half2*)&v2.y);
            a2.x += p.x; a2.y += p.y; a2.z += q.x; a2.w += q.y;
            p = __half22float2(*(__half2*)&v3.x);
            q = __half22float2(*(__half2*)&v3.y);
            a3.x += p.x; a3.y += p.y; a3.z += q.x; a3.w += q.y;
        }
        for (; k < cnt; k++) {
            int r0 = __shfl_sync(0xffffffffu, r, k);
            uint2 v0 = HS[(size_t)r0 * 32 + lane];
            float2 p = __half22float2(*(__half2*)&v0.x);
            float2 q = __half22float2(*(__half2*)&v0.y);
            a0.x += p.x; a0.y += p.y; a0.z += q.x; a0.w += q.y;
        }
    }

    float4 acc = make_float4(a0.x + a1.x + a2.x + a3.x,
                             a0.y + a1.y + a2.y + a3.y,
                             a0.z + a1.z + a2.z + a3.z,
                             a0.w + a1.w + a2.w + a3.w);

    float4 bb = ((const float4*)bias)[lane];
    float4 x;
    x.x = fmaxf(fmaf(dinv_c, acc.x, bb.x), 0.f);
    x.y = fmaxf(fmaf(dinv_c, acc.y, bb.y), 0.f);
    x.z = fmaxf(fmaf(dinv_c, acc.z, bb.z), 0.f);
    x.w = fmaxf(fmaf(dinv_c, acc.w, bb.w), 0.f);

    if (use_out) {
        ((float4*)(out + (size_t)node * D))[lane] = x;
    } else {
        uint2 o;
        __half2 h;
        h = __floats2half2_rn(x.x, x.y); o.x = *(uint32_t*)&h;
        h = __floats2half2_rn(x.z, x.w); o.y = *(uint32_t*)&h;
        ((uint2*)(g_xh + (size_t)node * D))[lane] = o;
    }
}

// ===========================================================================
// Launch
// ===========================================================================
extern "C" void kernel_launch(void* const* d_in, const int* in_sizes, int n_in,
                              void* d_out, int out_size) {
    const void* edge = d_in[0];
    const float* emb = (const float*)d_in[1];
    const float* Ws  = (const float*)d_in[2];
    const float* bs  = (const float*)d_in[3];
    float* out = (float*)d_out;

    __half* g_w16_p;
    cudaGetSymbolAddress((void**)&g_w16_p, g_w16);

    static bool attr_done = false;
    if (!attr_done) {
        cudaFuncSetAttribute(k_gemm<true>,
                             cudaFuncAttributeMaxDynamicSharedMemorySize, GEMM_SMEM);
        cudaFuncSetAttribute(k_gemm<false>,
                             cudaFuncAttributeMaxDynamicSharedMemorySize, GEMM_SMEM);
        attr_done = true;
    }

    const int nb_nodes = (N_NODES + 255) / 256;
    const int nb_edges = (N_EDGES + 255) / 256;

    k_detect_zero_w<<<nb_nodes, 256>>>((const unsigned int*)edge, Ws);
    k_hist_pack<<<nb_edges, 256>>>(edge);
    k_scan1<<<N_SCAN_BLOCKS, SCAN_B>>>();
    k_scan23<<<nb_nodes, 256>>>();
    k_fill<<<nb_edges, 256>>>(edge);

    const int gemm_blocks = N_PAD / 128;                 // 782
    const int agg_blocks = (N_NODES * 32 + 255) / 256;   // 12500

    // Layer 0 (reads emb fp32 directly)
    k_gemm<true><<<gemm_blocks, 256, GEMM_SMEM>>>(g_w16_p + 0 * D * D, emb);
    k_aggregate<<<agg_blocks, 256>>>(bs + 0 * D, out, 0);
    // Layer 1
    k_gemm<false><<<gemm_blocks, 256, GEMM_SMEM>>>(g_w16_p + 1 * D * D, nullptr);
    k_aggregate<<<agg_blocks, 256>>>(bs + 1 * D, out, 0);
    // Layer 2 -> d_out (ReLU in aggregate)
    k_gemm<false><<<gemm_blocks, 256, GEMM_SMEM>>>(g_w16_p + 2 * D * D, nullptr);
    k_aggregate<<<agg_blocks, 256>>>(bs + 2 * D, out, 1);
}

// round 15
// speedup vs baseline: 1.1675x; 1.1171x over previous
#include <cuda_runtime.h>
#include <cuda_fp16.h>
#include <mma.h>
#include <cstdint>

#define N_NODES 100000
#define N_PAD   100096        // multiple of 128-row tiles
#define N_EDGES 1600000
#define D 128
#define SCAN_B 1024
#define N_SCAN_BLOCKS ((N_NODES + SCAN_B - 1) / SCAN_B)   // 98

using namespace nvcuda;

// Scratch (allocation-free rule: __device__ globals; zero-initialized)
__device__ __half g_hs[(size_t)N_PAD * D];   // hs = (x @ W) * dinv[row], fp16
__device__ __half g_xh[(size_t)N_PAD * D];   // activations, fp16 (pad rows 0)
__device__ __half g_w16[3 * D * D];          // weights, fp16
__device__ float  g_dinv[N_NODES];
__device__ int    g_is64;
__device__ unsigned g_epack[N_EDGES];        // (col<<15) | slot
__device__ int    g_cnt[N_NODES];
__device__ int    g_rowptr[N_NODES + 1];
__device__ int    g_src[N_EDGES];
__device__ int    g_bsum[N_SCAN_BLOCKS];

// ===========================================================================
// Setup (exact R12 kernels)
// ===========================================================================

// zero cnt everywhere; block 0 additionally detects edge dtype
__global__ void k_detect_zero(const unsigned int* __restrict__ buf) {
    int i = blockIdx.x * blockDim.x + threadIdx.x;
    if (i < N_NODES) g_cnt[i] = 0;
    if (blockIdx.x == 0) {
        __shared__ unsigned int acc;
        if (threadIdx.x == 0) acc = 0u;
        __syncthreads();
        unsigned int local = 0u;
        for (int k = threadIdx.x; k < 4096; k += blockDim.x)
            local |= buf[2 * k + 1];
        atomicOr(&acc, local);
        __syncthreads();
        if (threadIdx.x == 0) g_is64 = (acc == 0u) ? 1 : 0;
    }
}

// histogram target degree; the atomic return value doubles as the CSR slot
__global__ void k_hist_pack(const void* __restrict__ buf) {
    int e = blockIdx.x * blockDim.x + threadIdx.x;
    if (e >= N_EDGES) return;
    int c;
    if (g_is64) c = (int)((const long long*)buf)[e + N_EDGES];
    else        c = ((const int*)buf)[e + N_EDGES];
    int pos = atomicAdd(&g_cnt[c], 1);
    g_epack[e] = ((unsigned)c << 15) | ((unsigned)pos & 0x7FFFu);
}

// block-level exclusive scan of degrees; also dinv = rsqrt(1+deg)
__global__ void __launch_bounds__(SCAN_B)
k_scan1() {
    __shared__ int s[SCAN_B];
    int i = blockIdx.x * SCAN_B + threadIdx.x;
    int v = (i < N_NODES) ? g_cnt[i] : 0;
    if (i < N_NODES) g_dinv[i] = rsqrtf(1.0f + (float)v);
    s[threadIdx.x] = v;
    __syncthreads();
#pragma unroll
    for (int off = 1; off < SCAN_B; off <<= 1) {
        int t = (threadIdx.x >= off) ? s[threadIdx.x - off] : 0;
        __syncthreads();
        s[threadIdx.x] += t;
        __syncthreads();
    }
    if (i < N_NODES) g_rowptr[i] = s[threadIdx.x] - v;
    if (threadIdx.x == SCAN_B - 1) g_bsum[blockIdx.x] = s[SCAN_B - 1];
}

// every block redundantly scans the 98 block sums, then applies to its nodes
__global__ void k_scan23() {
    __shared__ int s[128];
    __shared__ int ex[128];
    int t = threadIdx.x;
    int v = 0;
    if (t < 128) {
        v = (t < N_SCAN_BLOCKS) ? g_bsum[t] : 0;
        s[t] = v;
    }
    __syncthreads();
#pragma unroll
    for (int off = 1; off < 128; off <<= 1) {
        int tv = 0;
        if (t < 128 && t >= off) tv = s[t - off];
        __syncthreads();
        if (t < 128) s[t] += tv;
        __syncthreads();
    }
    if (t < 128) ex[t] = s[t] - v;   // exclusive
    __syncthreads();
    int i = blockIdx.x * blockDim.x + t;
    if (i < N_NODES) g_rowptr[i] += ex[i >> 10];
    if (i == 0) g_rowptr[N_NODES] = N_EDGES;
}

// atomic-free CSR fill using the packed (col, slot)
__global__ void k_fill(const void* __restrict__ buf) {
    int e = blockIdx.x * blockDim.x + threadIdx.x;
    if (e >= N_EDGES) return;
    unsigned p = g_epack[e];
    int c = (int)(p >> 15);
    int pos = (int)(p & 0x7FFFu);
    int r;
    if (g_is64) r = (int)((const long long*)buf)[e];
    else        r = ((const int*)buf)[e];
    int idx = g_rowptr[c] + pos;
    if (idx < N_EDGES) g_src[idx] = r;
}

// W -> fp16
__global__ void k_w2h(const float* __restrict__ Ws) {
    int i = blockIdx.x * blockDim.x + threadIdx.x;
    if (i < 3 * D * D) g_w16[i] = __float2half_rn(Ws[i]);
}

// ===========================================================================
// fp16 wmma GEMM (exact R12): 128x128 tile, conflict-free LDSM (LDH=136).
// ===========================================================================
#define LDH 136
#define GEMM_SMEM (2 * 128 * LDH * 2)      // 69632 B

template<bool FROM_EMB>
__global__ void __launch_bounds__(256, 2)
k_gemm(const __half* __restrict__ Wl, const float* __restrict__ emb) {
    extern __shared__ __half smh[];
    __half* As = smh;                 // [128][LDH]
    __half* Wsm = smh + 128 * LDH;    // [128][LDH]

    const int tid = threadIdx.x;
    const int wid = tid >> 5;
    const int lane = tid & 31;
    const int wm = wid >> 1;
    const int wn = wid & 1;
    const int row0 = blockIdx.x * 128;

    for (int idx = tid; idx < 2048; idx += 256) {
        int r = idx >> 4, c8 = idx & 15;
        uint4 v = ((const uint4*)(Wl + r * D))[c8];
        *(uint4*)(Wsm + r * LDH + c8 * 8) = v;
    }
    for (int idx = tid; idx < 2048; idx += 256) {
        int r = idx >> 4, c8 = idx & 15;
        int row = row0 + r;
        uint4 v = make_uint4(0u, 0u, 0u, 0u);
        if (row < N_NODES) {
            if (FROM_EMB) {
                const float4* s = (const float4*)(emb + (size_t)row * D) + c8 * 2;
                float4 v0 = s[0], v1 = s[1];
                __half2 h;
                h = __floats2half2_rn(v0.x, v0.y); v.x = *(uint32_t*)&h;
                h = __floats2half2_rn(v0.z, v0.w); v.y = *(uint32_t*)&h;
                h = __floats2half2_rn(v1.x, v1.y); v.z = *(uint32_t*)&h;
                h = __floats2half2_rn(v1.z, v1.w); v.w = *(uint32_t*)&h;
            } else {
                v = ((const uint4*)(g_xh + (size_t)row * D))[c8];
            }
        }
        *(uint4*)(As + r * LDH + c8 * 8) = v;
    }
    __syncthreads();

    wmma::fragment<wmma::accumulator, 16, 16, 16, float> acc[2][4];
#pragma unroll
    for (int i = 0; i < 2; i++)
#pragma unroll
        for (int j = 0; j < 4; j++) wmma::fill_fragment(acc[i][j], 0.0f);

#pragma unroll
    for (int k = 0; k < 8; k++) {
        wmma::fragment<wmma::matrix_a, 16, 16, 16, __half, wmma::row_major> a[2];
        wmma::fragment<wmma::matrix_b, 16, 16, 16, __half, wmma::row_major> b[4];
#pragma unroll
        for (int i = 0; i < 2; i++)
            wmma::load_matrix_sync(a[i], As + (wm * 32 + i * 16) * LDH + k * 16,
                                   LDH);
#pragma unroll
        for (int j = 0; j < 4; j++)
            wmma::load_matrix_sync(b[j], Wsm + (k * 16) * LDH + wn * 64 + j * 16,
                                   LDH);
#pragma unroll
        for (int i = 0; i < 2; i++)
#pragma unroll
            for (int j = 0; j < 4; j++)
                wmma::mma_sync(acc[i][j], a[i], b[j], acc[i][j]);
    }

    __syncthreads();
    float* stage = reinterpret_cast<float*>(smh) + wid * (16 * 68);
#pragma unroll
    for (int i = 0; i < 2; i++) {
#pragma unroll
        for (int j = 0; j < 4; j++)
            wmma::store_matrix_sync(stage + j * 16, acc[i][j], 68,
                                    wmma::mem_row_major);
        __syncwarp();
        int r = lane >> 1;
        int ch = (lane & 1) * 32;
        int row = row0 + wm * 32 + i * 16 + r;
        float s = (row < N_NODES) ? g_dinv[row] : 0.0f;
        const float* src = stage + r * 68 + ch;
        if (row < N_NODES) {
            uint4* dst = (uint4*)(g_hs + (size_t)row * D + wn * 64 + ch);
#pragma unroll
            for (int q = 0; q < 4; q++) {
                uint4 o;
                __half2 h;
                h = __floats2half2_rn(src[q * 8 + 0] * s, src[q * 8 + 1] * s);
                o.x = *(uint32_t*)&h;
                h = __floats2half2_rn(src[q * 8 + 2] * s, src[q * 8 + 3] * s);
                o.y = *(uint32_t*)&h;
                h = __floats2half2_rn(src[q * 8 + 4] * s, src[q * 8 + 5] * s);
                o.z = *(uint32_t*)&h;
                h = __floats2half2_rn(src[q * 8 + 6] * s, src[q * 8 + 7] * s);
                o.w = *(uint32_t*)&h;
                dst[q] = o;
            }
        }
        __syncwarp();
    }
}

// ===========================================================================
// Aggregation (exact R12 proven shape): warp per node, full-warp uint2 gather,
// 2-deep unroll / dual fp32 accumulators.
// ===========================================================================
__global__ void __launch_bounds__(256)
k_aggregate(const float* __restrict__ bias, float* __restrict__ out,
            int use_out) {
    int node = (blockIdx.x * blockDim.x + threadIdx.x) >> 5;
    int lane = threadIdx.x & 31;
    if (node >= N_NODES) return;

    float dinv_c = g_dinv[node];
    const uint2* HS = (const uint2*)g_hs;   // 32 uint2 per row

    uint2 v = HS[(size_t)node * 32 + lane];
    float2 f0 = __half22float2(*(__half2*)&v.x);
    float2 f1 = __half22float2(*(__half2*)&v.y);
    float4 acc0 = make_float4(f0.x, f0.y, f1.x, f1.y);
    float4 acc1 = make_float4(0.f, 0.f, 0.f, 0.f);

    int beg = g_rowptr[node];
    int end = g_rowptr[node + 1];
    for (int base = beg; base < end; base += 32) {
        int j = base + lane;
        int r = (j < end) ? g_src[j] : 0;
        int cnt = min(32, end - base);
        int k = 0;
        for (; k + 1 < cnt; k += 2) {
            int r0 = __shfl_sync(0xffffffffu, r, k);
            int r1 = __shfl_sync(0xffffffffu, r, k + 1);
            uint2 v0 = HS[(size_t)r0 * 32 + lane];
            uint2 v1 = HS[(size_t)r1 * 32 + lane];
            float2 a0 = __half22float2(*(__half2*)&v0.x);
            float2 a1 = __half22float2(*(__half2*)&v0.y);
            float2 b0 = __half22float2(*(__half2*)&v1.x);
            float2 b1 = __half22float2(*(__half2*)&v1.y);
            acc0.x += a0.x; acc0.y += a0.y; acc0.z += a1.x; acc0.w += a1.y;
            acc1.x += b0.x; acc1.y += b0.y; acc1.z += b1.x; acc1.w += b1.y;
        }
        if (k < cnt) {
            int r0 = __shfl_sync(0xffffffffu, r, k);
            uint2 v0 = HS[(size_t)r0 * 32 + lane];
            float2 a0 = __half22float2(*(__half2*)&v0.x);
            float2 a1 = __half22float2(*(__half2*)&v0.y);
            acc0.x += a0.x; acc0.y += a0.y; acc0.z += a1.x; acc0.w += a1.y;
        }
    }

    float4 bb = ((const float4*)bias)[lane];
    float4 x;
    x.x = fmaxf(fmaf(dinv_c, acc0.x + acc1.x, bb.x), 0.f);
    x.y = fmaxf(fmaf(dinv_c, acc0.y + acc1.y, bb.y), 0.f);
    x.z = fmaxf(fmaf(dinv_c, acc0.z + acc1.z, bb.z), 0.f);
    x.w = fmaxf(fmaf(dinv_c, acc0.w + acc1.w, bb.w), 0.f);

    if (use_out) {
        ((float4*)(out + (size_t)node * D))[lane] = x;
    } else {
        uint2 o;
        __half2 h;
        h = __floats2half2_rn(x.x, x.y); o.x = *(uint32_t*)&h;
        h = __floats2half2_rn(x.z, x.w); o.y = *(uint32_t*)&h;
        ((uint2*)(g_xh + (size_t)node * D))[lane] = o;
    }
}

// ===========================================================================
// Launch — fork {scan23, fill} onto a side stream, overlapped with GEMM-0.
// Stream/events created once on the first (uncaptured) correctness call;
// under graph capture the event fork/join becomes parallel graph branches.
// ===========================================================================
extern "C" void kernel_launch(void* const* d_in, const int* in_sizes, int n_in,
                              void* d_out, int out_size) {
    const void* edge = d_in[0];
    const float* emb = (const float*)d_in[1];
    const float* Ws  = (const float*)d_in[2];
    const float* bs  = (const float*)d_in[3];
    float* out = (float*)d_out;

    __half* g_w16_p;
    cudaGetSymbolAddress((void**)&g_w16_p, g_w16);

    static cudaStream_t s2;
    static cudaEvent_t e1, e2;
    static bool init_done = false;
    if (!init_done) {
        cudaFuncSetAttribute(k_gemm<true>,
                             cudaFuncAttributeMaxDynamicSharedMemorySize, GEMM_SMEM);
        cudaFuncSetAttribute(k_gemm<false>,
                             cudaFuncAttributeMaxDynamicSharedMemorySize, GEMM_SMEM);
        cudaStreamCreateWithFlags(&s2, cudaStreamNonBlocking);
        cudaEventCreateWithFlags(&e1, cudaEventDisableTiming);
        cudaEventCreateWithFlags(&e2, cudaEventDisableTiming);
        init_done = true;
    }

    const int nb_nodes = (N_NODES + 255) / 256;
    const int nb_edges = (N_EDGES + 255) / 256;
    const int gemm_blocks = N_PAD / 128;                 // 782
    const int agg_blocks = (N_NODES * 32 + 255) / 256;   // 12500

    // Main-stream setup chain
    k_detect_zero<<<nb_nodes, 256>>>((const unsigned int*)edge);
    k_w2h<<<(3 * D * D + 255) / 256, 256>>>(Ws);
    k_hist_pack<<<nb_edges, 256>>>(edge);
    k_scan1<<<N_SCAN_BLOCKS, SCAN_B>>>();

    // Fork: CSR finalize (only needed by aggregate) runs on s2,
    // concurrent with layer-0 GEMM on the main stream.
    cudaEventRecord(e1, 0);
    cudaStreamWaitEvent(s2, e1, 0);
    k_scan23<<<nb_nodes, 256, 0, s2>>>();
    k_fill<<<nb_edges, 256, 0, s2>>>(edge);
    cudaEventRecord(e2, s2);

    // Layer 0 GEMM (needs dinv + g_w16 only)
    k_gemm<true><<<gemm_blocks, 256, GEMM_SMEM>>>(g_w16_p + 0 * D * D, emb);

    // Join before first aggregation
    cudaStreamWaitEvent(0, e2, 0);
    k_aggregate<<<agg_blocks, 256>>>(bs + 0 * D, out, 0);
    // Layer 1
    k_gemm<false><<<gemm_blocks, 256, GEMM_SMEM>>>(g_w16_p + 1 * D * D, nullptr);
    k_aggregate<<<agg_blocks, 256>>>(bs + 1 * D, out, 0);
    // Layer 2 -> d_out (ReLU in aggregate)
    k_gemm<false><<<gemm_blocks, 256, GEMM_SMEM>>>(g_w16_p + 2 * D * D, nullptr);
    k_aggregate<<<agg_blocks, 256>>>(bs + 2 * D, out, 1);
}